// round 2
// baseline (speedup 1.0000x reference)
#include <cuda_runtime.h>
#include <cuda_bf16.h>
#include <cstdint>

// ============================================================================
// out[B, OUT] = x[B, IN] @ W[OUT, IN]^T + b[OUT], fp32, 4096^3.
// Plain sm_103 target (no tcgen05!) -> baseline mma.sync bf16 HMMA path.
// fp32 -> bf16 hi/lo split, 3-term product (hi*hi + hi*lo + lo*hi).
// ============================================================================

#define DIM 4096

// Static device scratch (allocation-free rule: __device__ globals are allowed)
__device__ __nv_bfloat16 g_xhi[(size_t)DIM * DIM];
__device__ __nv_bfloat16 g_xlo[(size_t)DIM * DIM];
__device__ __nv_bfloat16 g_whi[(size_t)DIM * DIM];
__device__ __nv_bfloat16 g_wlo[(size_t)DIM * DIM];

// ----------------------------------------------------------------------------
// helpers
// ----------------------------------------------------------------------------
__device__ __forceinline__ uint32_t smem_u32(const void* p) {
    uint32_t a;
    asm("{ .reg .u64 t; cvta.to.shared.u64 t, %1; cvt.u32.u64 %0, t; }"
        : "=r"(a) : "l"(p));
    return a;
}

__device__ __forceinline__ void cp16(uint32_t dst, const void* src) {
    asm volatile("cp.async.cg.shared.global [%0], [%1], 16;"
                 :: "r"(dst), "l"(src));
}
#define CP_COMMIT() asm volatile("cp.async.commit_group;" ::: "memory")
#define CP_WAIT2()  asm volatile("cp.async.wait_group 2;"  ::: "memory")

__device__ __forceinline__ void ldm4(uint32_t* r, uint32_t addr) {
    asm volatile("ldmatrix.sync.aligned.m8n8.x4.shared.b16 {%0,%1,%2,%3}, [%4];"
                 : "=r"(r[0]), "=r"(r[1]), "=r"(r[2]), "=r"(r[3]) : "r"(addr));
}

__device__ __forceinline__ void mma16816(float* d, const uint32_t* a, const uint32_t* b) {
    asm volatile(
        "mma.sync.aligned.m16n8k16.row.col.f32.bf16.bf16.f32 "
        "{%0,%1,%2,%3}, {%4,%5,%6,%7}, {%8,%9}, {%0,%1,%2,%3};"
        : "+f"(d[0]), "+f"(d[1]), "+f"(d[2]), "+f"(d[3])
        : "r"(a[0]), "r"(a[1]), "r"(a[2]), "r"(a[3]), "r"(b[0]), "r"(b[1]));
}

// ----------------------------------------------------------------------------
// Kernel 1: fp32 -> bf16 hi/lo split
// ----------------------------------------------------------------------------
struct __align__(8) bf4 { __nv_bfloat162 a, b; };

__global__ void __launch_bounds__(256) convert_split(const float* __restrict__ src, int which) {
    __nv_bfloat16* __restrict__ hi = which ? g_whi : g_xhi;
    __nv_bfloat16* __restrict__ lo = which ? g_wlo : g_xlo;
    const int n4 = (DIM * DIM) / 4;
    const float4* __restrict__ s4 = (const float4*)src;
    for (int i = blockIdx.x * blockDim.x + threadIdx.x; i < n4;
         i += gridDim.x * blockDim.x) {
        float4 f = s4[i];
        __nv_bfloat16 h0 = __float2bfloat16_rn(f.x);
        __nv_bfloat16 h1 = __float2bfloat16_rn(f.y);
        __nv_bfloat16 h2 = __float2bfloat16_rn(f.z);
        __nv_bfloat16 h3 = __float2bfloat16_rn(f.w);
        __nv_bfloat16 l0 = __float2bfloat16_rn(f.x - __bfloat162float(h0));
        __nv_bfloat16 l1 = __float2bfloat16_rn(f.y - __bfloat162float(h1));
        __nv_bfloat16 l2 = __float2bfloat16_rn(f.z - __bfloat162float(h2));
        __nv_bfloat16 l3 = __float2bfloat16_rn(f.w - __bfloat162float(h3));
        bf4 H; H.a = __halves2bfloat162(h0, h1); H.b = __halves2bfloat162(h2, h3);
        bf4 L; L.a = __halves2bfloat162(l0, l1); L.b = __halves2bfloat162(l2, l3);
        ((bf4*)hi)[i] = H;
        ((bf4*)lo)[i] = L;
    }
}

// ----------------------------------------------------------------------------
// Kernel 2: mma.sync bf16x3 GEMM. BM=128 BN=128 BK=32, 4 stages, 8 warps.
// ----------------------------------------------------------------------------
static constexpr int BM = 128;
static constexpr int BN = 128;
static constexpr int BK = 32;
static constexpr int STAGES = 4;
static constexpr int NK = DIM / BK;              // 128 iterations

static constexpr int TILE_B = BM * BK * 2;       // 8192 bytes per operand tile
static constexpr int OFF_AHI = 0;
static constexpr int OFF_ALO = TILE_B;
static constexpr int OFF_BHI = 2 * TILE_B;
static constexpr int OFF_BLO = 3 * TILE_B;
static constexpr int STAGE_B = 4 * TILE_B;       // 32768
static constexpr int SMEM_BYTES = STAGES * STAGE_B;  // 131072

// swizzled 16B-unit offset within a tile: row r (64B rows), unit u (0..3)
__device__ __forceinline__ uint32_t sw_off(int r, int u) {
    return (uint32_t)(r * 64 + ((u ^ ((r >> 1) & 3)) << 4));
}

__device__ __forceinline__ void load_stage(uint32_t st, int tm, int tn, int k0, int tid) {
#pragma unroll
    for (int i = 0; i < 2; i++) {
        int c = tid + i * 256;
        int r = c >> 2, u = c & 3;
        uint32_t sw = sw_off(r, u);
        size_t gx = (size_t)(tm * BM + r) * DIM + k0 + u * 8;
        size_t gw = (size_t)(tn * BN + r) * DIM + k0 + u * 8;
        cp16(st + OFF_AHI + sw, g_xhi + gx);
        cp16(st + OFF_ALO + sw, g_xlo + gx);
        cp16(st + OFF_BHI + sw, g_whi + gw);
        cp16(st + OFF_BLO + sw, g_wlo + gw);
    }
}

__global__ void __launch_bounds__(256, 1)
gemm_kernel(const float* __restrict__ bias, float* __restrict__ out) {
    extern __shared__ char smem[];
    const uint32_t sb = smem_u32(smem);
    const int tid = threadIdx.x;
    const int wid = tid >> 5;
    const int lane = tid & 31;
    const int warp_m = wid & 3;      // 4 warps along M (32 rows each)
    const int warp_n = wid >> 2;     // 2 warps along N (64 cols each)

    // Raster: 64-CTA groups (8 M-tiles x 8 N-tiles) -> ~64MB wave working set
    const int bid = blockIdx.x;
    const int g = bid >> 6;                 // 0..15
    const int tm = (g & 3) * 8 + (bid & 7);
    const int tn = (g >> 2) * 8 + ((bid >> 3) & 7);

    // --- ldmatrix lane addressing (precomputed) ---
    // A: matrices (m0,k0),(m8,k0),(m0,k8),(m8,k8) <- lane groups 0..3
    const int a_idx = lane >> 3;
    const int a_row = warp_m * 32 + (lane & 7) + (a_idx & 1) * 8;
    const int a_kk  = a_idx >> 1;
    const int a_sw  = (a_row >> 1) & 3;
    // B: matrices (n0,k0),(n0,k8),(n8,k0),(n8,k8)
    const int b_idx = lane >> 3;
    const int b_rr  = warp_n * 64 + (lane & 7) + (b_idx >> 1) * 8;  // + p*16
    const int b_kk  = b_idx & 1;
    const int b_sw  = (b_rr >> 1) & 3;   // p*16 doesn't change ((row>>1)&3)

    uint32_t ua[2], ub[2];
#pragma unroll
    for (int ks = 0; ks < 2; ks++) {
        ua[ks] = (uint32_t)(((ks * 2 + a_kk) ^ a_sw) << 4);
        ub[ks] = (uint32_t)(((ks * 2 + b_kk) ^ b_sw) << 4);
    }
    const uint32_t a_base = (uint32_t)(a_row * 64);
    const uint32_t b_base = (uint32_t)(b_rr * 64);

    float acc[2][8][4];
#pragma unroll
    for (int mt = 0; mt < 2; mt++)
#pragma unroll
        for (int nt = 0; nt < 8; nt++)
#pragma unroll
            for (int j = 0; j < 4; j++) acc[mt][nt][j] = 0.f;

    // Prologue: fill 3 stages
#pragma unroll
    for (int s = 0; s < STAGES - 1; s++) {
        load_stage(sb + s * STAGE_B, tm, tn, s * BK, tid);
        CP_COMMIT();
    }

    for (int kt = 0; kt < NK; kt++) {
        CP_WAIT2();
        __syncthreads();
        const uint32_t stg = sb + (kt & (STAGES - 1)) * STAGE_B;

#pragma unroll
        for (int ks = 0; ks < 2; ks++) {
            uint32_t ahi[2][4], alo[2][4];
            ldm4(ahi[0], stg + OFF_AHI + a_base + ua[ks]);
            ldm4(ahi[1], stg + OFF_AHI + a_base + 1024 + ua[ks]);
            ldm4(alo[0], stg + OFF_ALO + a_base + ua[ks]);
            ldm4(alo[1], stg + OFF_ALO + a_base + 1024 + ua[ks]);
            uint32_t bhi[4][4], blo[4][4];
#pragma unroll
            for (int p = 0; p < 4; p++) {
                ldm4(bhi[p], stg + OFF_BHI + b_base + p * 1024 + ub[ks]);
                ldm4(blo[p], stg + OFF_BLO + b_base + p * 1024 + ub[ks]);
            }
#pragma unroll
            for (int mt = 0; mt < 2; mt++) {
#pragma unroll
                for (int nt = 0; nt < 8; nt++) {
                    const int p = nt >> 1, h = (nt & 1) * 2;
                    mma16816(acc[mt][nt], ahi[mt], &bhi[p][h]);
                    mma16816(acc[mt][nt], ahi[mt], &blo[p][h]);
                    mma16816(acc[mt][nt], alo[mt], &bhi[p][h]);
                }
            }
        }

        const int kn = kt + STAGES - 1;
        if (kn < NK)
            load_stage(sb + (kn & (STAGES - 1)) * STAGE_B, tm, tn, kn * BK, tid);
        CP_COMMIT();   // unconditional: keeps wait_group accounting exact
    }

    // Epilogue: d0,d1 -> (row l/4, col 2(l%4)+{0,1}); d2,d3 -> row+8
    const int m0 = tm * BM + warp_m * 32;
    const int n0 = tn * BN + warp_n * 64;
    const int er = lane >> 2;
    const int ec = (lane & 3) * 2;
#pragma unroll
    for (int nt = 0; nt < 8; nt++) {
        const int col = n0 + nt * 8 + ec;
        const float b0 = __ldg(bias + col);
        const float b1 = __ldg(bias + col + 1);
#pragma unroll
        for (int mt = 0; mt < 2; mt++) {
            const int row = m0 + mt * 16 + er;
            float2 v0 = make_float2(acc[mt][nt][0] + b0, acc[mt][nt][1] + b1);
            float2 v1 = make_float2(acc[mt][nt][2] + b0, acc[mt][nt][3] + b1);
            *(float2*)(out + (size_t)row * DIM + col) = v0;
            *(float2*)(out + (size_t)(row + 8) * DIM + col) = v1;
        }
    }
}

// ----------------------------------------------------------------------------
// kernel_launch
// ----------------------------------------------------------------------------
extern "C" void kernel_launch(void* const* d_in, const int* in_sizes, int n_in,
                              void* d_out, int out_size) {
    const float* x = (const float*)d_in[0];
    const float* W = (const float*)d_in[1];
    const float* b = (const float*)d_in[2];
    float* out = (float*)d_out;

    cudaFuncSetAttribute(gemm_kernel,
                         cudaFuncAttributeMaxDynamicSharedMemorySize, SMEM_BYTES);

    convert_split<<<4096, 256>>>(x, 0);
    convert_split<<<4096, 256>>>(W, 1);

    const int grid = (DIM / BM) * (DIM / BN);   // 32 * 32 = 1024
    gemm_kernel<<<grid, 256, SMEM_BYTES>>>(b, out);
}